// round 10
// baseline (speedup 1.0000x reference)
#include <cuda_runtime.h>
#include <cuda_bf16.h>
#include <stdint.h>
#include <math.h>

#define NN 50000
#define EE 800000
#define HID 128
#define GG 128
#define LAT 32
#define NEG 0.2f
#define XK 64

// ---------------- scratch (static device memory; zero-initialized) ----------------
__device__ float g_h[NN * HID];          // gemm output (fp32) for agg
__device__ __nv_bfloat16 g_yh[NN * HID]; // agg output hi
__device__ __nv_bfloat16 g_yl[NN * HID]; // agg output lo
__device__ __nv_bfloat16 g_xh[NN * XK];  // layer-0 input hi
__device__ __nv_bfloat16 g_xl[NN * XK];
__device__ __nv_bfloat16 g_w0h[128 * 64],  g_w0l[128 * 64];    // W^T [n][k]
__device__ __nv_bfloat16 g_w1h[128 * 128], g_w1l[128 * 128];
__device__ __nv_bfloat16 g_w2h[128 * 128], g_w2l[128 * 128];
__device__ float g_as[NN * 4];
__device__ float g_ad[NN * 4];
__device__ int   g_deg[NN];              // invariant: zero before/after each launch
__device__ int   g_rowoff[NN + 1];
__device__ int   g_cur[NN];
__device__ int   g_csr[EE + NN];
__device__ int   g_goff[GG + 1];
__device__ float g_pool[GG * HID];

__device__ __forceinline__ void bsplit(float v, __nv_bfloat16& h, __nv_bfloat16& l) {
    h = __float2bfloat16(v);
    l = __float2bfloat16(v - __bfloat162float(h));
}

// ---------------- prep: split x and W^T into bf16 hi/lo ----------------
__global__ void prep_kernel(const float* __restrict__ x,  const float* __restrict__ W0,
                            const float* __restrict__ W1, const float* __restrict__ W2)
{
    int i = blockIdx.x * blockDim.x + threadIdx.x;
    if (i < NN * XK) {
        bsplit(x[i], g_xh[i], g_xl[i]);
        return;
    }
    i -= NN * XK;
    if (i < 128 * 64) {
        int n = i / 64, k = i % 64;
        bsplit(W0[k * 128 + n], g_w0h[n * 64 + k], g_w0l[n * 64 + k]);
        return;
    }
    i -= 128 * 64;
    if (i < 128 * 128) {
        int n = i >> 7, k = i & 127;
        bsplit(W1[k * 128 + n], g_w1h[n * 128 + k], g_w1l[n * 128 + k]);
        return;
    }
    i -= 128 * 128;
    if (i < 128 * 128) {
        int n = i >> 7, k = i & 127;
        bsplit(W2[k * 128 + n], g_w2h[n * 128 + k], g_w2l[n * 128 + k]);
    }
}

// ---------------- CSR build ----------------
__global__ void hist_kernel(const int* __restrict__ dst) {
    int i = blockIdx.x * blockDim.x + threadIdx.x;
    if (i < EE) atomicAdd(&g_deg[dst[i]], 1);
}

__global__ void scan_kernel() {
    __shared__ int sums[1024];
    const int T = 1024;
    int t = threadIdx.x;
    const int chunk = (NN + T - 1) / T;
    int start = t * chunk;
    int end = min(start + chunk, NN);
    int s = 0;
    for (int i = start; i < end; i++) s += g_deg[i] + 1;
    sums[t] = s;
    __syncthreads();
    for (int off = 1; off < T; off <<= 1) {
        int v = 0;
        if (t >= off) v = sums[t - off];
        __syncthreads();
        if (t >= off) sums[t] += v;
        __syncthreads();
    }
    int base = (t == 0) ? 0 : sums[t - 1];
    for (int i = start; i < end; i++) {
        g_rowoff[i] = base;
        g_cur[i] = base;
        base += g_deg[i] + 1;
        g_deg[i] = 0;
    }
    if (t == 0) g_rowoff[NN] = sums[T - 1];
}

__global__ void scatter_kernel(const int* __restrict__ src, const int* __restrict__ dst) {
    int i = blockIdx.x * blockDim.x + threadIdx.x;
    if (i < EE) {
        int d = dst[i];
        int pos = atomicAdd(&g_cur[d], 1);
        g_csr[pos] = src[i];
    } else if (i < EE + NN) {
        int n = i - EE;
        int pos = atomicAdd(&g_cur[n], 1);
        g_csr[pos] = n;
    }
}

__global__ void gbound_kernel(const int* __restrict__ batch) {
    int i = blockIdx.x * blockDim.x + threadIdx.x;
    if (i >= NN) return;
    int b = batch[i];
    int prev = (i == 0) ? -1 : batch[i - 1];
    for (int g = prev + 1; g <= b; g++) g_goff[g] = i;
    if (i == NN - 1) {
        for (int g = b + 1; g <= GG; g++) g_goff[g] = NN;
    }
}

// ---------------- HMMA bf16 split GEMM + fused alpha ----------------------------
// D = Ah*Bh + Al*Bh + Ah*Bl (fp32 acc). A,B pre-split bf16 in gmem; B transposed [n][K].
#define ASTR 40

#define MMA16816(d, a, b0v, b1v) \
    asm volatile("mma.sync.aligned.m16n8k16.row.col.f32.bf16.bf16.f32 " \
        "{%0,%1,%2,%3}, {%4,%5,%6,%7}, {%8,%9}, {%0,%1,%2,%3};" \
        : "+f"((d)[0]), "+f"((d)[1]), "+f"((d)[2]), "+f"((d)[3]) \
        : "r"((a)[0]), "r"((a)[1]), "r"((a)[2]), "r"((a)[3]), "r"(b0v), "r"(b1v))

__global__ __launch_bounds__(256, 2) void gemm_kernel(
    const __nv_bfloat16* __restrict__ Ah, const __nv_bfloat16* __restrict__ Al,
    const __nv_bfloat16* __restrict__ Bh, const __nv_bfloat16* __restrict__ Bl,
    float* __restrict__ Out, int nrows, int K,
    const float* __restrict__ a_src, const float* __restrict__ a_dst)
{
    __shared__ __align__(16) __nv_bfloat16 Ah_s[128 * ASTR];
    __shared__ __align__(16) __nv_bfloat16 Al_s[128 * ASTR];
    __shared__ __align__(16) __nv_bfloat16 Bh_s[128 * ASTR];
    __shared__ __align__(16) __nv_bfloat16 Bl_s[128 * ASTR];
    __shared__ float spart[128][4][2];
    __shared__ float sAs[128], sAd[128];

    int tid = threadIdx.x;
    int wid = tid >> 5, lane = tid & 31;
    int g = lane >> 2, tg = lane & 3;
    int rbase = (wid >> 1) * 32;
    int cbase = (wid & 1) * 64;
    int row0 = blockIdx.x * 128;

    if (tid < 128) { sAs[tid] = a_src[tid]; sAd[tid] = a_dst[tid]; }

    float acc[2][8][4];
#pragma unroll
    for (int mt = 0; mt < 2; mt++)
#pragma unroll
        for (int nt = 0; nt < 8; nt++)
#pragma unroll
            for (int q = 0; q < 4; q++) acc[mt][nt][q] = 0.f;

    int lrow = tid >> 1, lhalf = tid & 1;
    int grow = row0 + lrow;
    bool valid = grow < nrows;

    const int NCH = K >> 5;
    for (int ch = 0; ch < NCH; ch++) {
        // A: row lrow, 16 bf16 (32B) at k = ch*32 + lhalf*16
        {
            uint4 vh0 = make_uint4(0, 0, 0, 0), vh1 = vh0, vl0 = vh0, vl1 = vh0;
            if (valid) {
                const uint4* ph = (const uint4*)(Ah + (size_t)grow * K + ch * 32 + lhalf * 16);
                const uint4* pl = (const uint4*)(Al + (size_t)grow * K + ch * 32 + lhalf * 16);
                vh0 = __ldg(ph); vh1 = __ldg(ph + 1);
                vl0 = __ldg(pl); vl1 = __ldg(pl + 1);
            }
            uint4* dh = (uint4*)&Ah_s[lrow * ASTR + lhalf * 16];
            uint4* dl = (uint4*)&Al_s[lrow * ASTR + lhalf * 16];
            dh[0] = vh0; dh[1] = vh1;
            dl[0] = vl0; dl[1] = vl1;
        }
        // B: n = lrow, same k range
        {
            const uint4* ph = (const uint4*)(Bh + (size_t)lrow * K + ch * 32 + lhalf * 16);
            const uint4* pl = (const uint4*)(Bl + (size_t)lrow * K + ch * 32 + lhalf * 16);
            uint4 vh0 = __ldg(ph), vh1 = __ldg(ph + 1);
            uint4 vl0 = __ldg(pl), vl1 = __ldg(pl + 1);
            uint4* dh = (uint4*)&Bh_s[lrow * ASTR + lhalf * 16];
            uint4* dl = (uint4*)&Bl_s[lrow * ASTR + lhalf * 16];
            dh[0] = vh0; dh[1] = vh1;
            dl[0] = vl0; dl[1] = vl1;
        }
        __syncthreads();

#pragma unroll
        for (int ks = 0; ks < 2; ks++) {
            int kb = ks * 16;
            uint32_t ah[2][4], al[2][4];
#pragma unroll
            for (int mt = 0; mt < 2; mt++) {
                int r = rbase + mt * 16 + g;
                const __nv_bfloat16* ap = &Ah_s[r * ASTR + kb + tg * 2];
                ah[mt][0] = *(const uint32_t*)ap;
                ah[mt][1] = *(const uint32_t*)(ap + 8 * ASTR);
                ah[mt][2] = *(const uint32_t*)(ap + 8);
                ah[mt][3] = *(const uint32_t*)(ap + 8 * ASTR + 8);
                const __nv_bfloat16* lp = &Al_s[r * ASTR + kb + tg * 2];
                al[mt][0] = *(const uint32_t*)lp;
                al[mt][1] = *(const uint32_t*)(lp + 8 * ASTR);
                al[mt][2] = *(const uint32_t*)(lp + 8);
                al[mt][3] = *(const uint32_t*)(lp + 8 * ASTR + 8);
            }
#pragma unroll
            for (int nt = 0; nt < 8; nt++) {
                int nb = cbase + nt * 8 + g;
                const __nv_bfloat16* bp = &Bh_s[nb * ASTR + kb + tg * 2];
                uint32_t bh0 = *(const uint32_t*)bp;
                uint32_t bh1 = *(const uint32_t*)(bp + 8);
                const __nv_bfloat16* qp = &Bl_s[nb * ASTR + kb + tg * 2];
                uint32_t bl0 = *(const uint32_t*)qp;
                uint32_t bl1 = *(const uint32_t*)(qp + 8);
#pragma unroll
                for (int mt = 0; mt < 2; mt++) {
                    MMA16816(acc[mt][nt], ah[mt], bh0, bh1);
                    MMA16816(acc[mt][nt], al[mt], bh0, bh1);
                    MMA16816(acc[mt][nt], ah[mt], bl0, bl1);
                }
            }
        }
        __syncthreads();
    }

    // ---- fused alpha partials ----
    {
        float pA[2][2][2], pD[2][2][2];
#pragma unroll
        for (int mt = 0; mt < 2; mt++)
#pragma unroll
            for (int sb = 0; sb < 2; sb++)
#pragma unroll
                for (int hh = 0; hh < 2; hh++) { pA[mt][sb][hh] = 0.f; pD[mt][sb][hh] = 0.f; }
#pragma unroll
        for (int mt = 0; mt < 2; mt++)
#pragma unroll
            for (int nt = 0; nt < 8; nt++) {
                int hh = nt >> 2;
                int c0 = cbase + nt * 8 + tg * 2;
                float a0 = sAs[c0], a1 = sAs[c0 + 1];
                float d0 = sAd[c0], d1 = sAd[c0 + 1];
                pA[mt][0][hh] += acc[mt][nt][0] * a0 + acc[mt][nt][1] * a1;
                pA[mt][1][hh] += acc[mt][nt][2] * a0 + acc[mt][nt][3] * a1;
                pD[mt][0][hh] += acc[mt][nt][0] * d0 + acc[mt][nt][1] * d1;
                pD[mt][1][hh] += acc[mt][nt][2] * d0 + acc[mt][nt][3] * d1;
            }
#pragma unroll
        for (int mt = 0; mt < 2; mt++)
#pragma unroll
            for (int sb = 0; sb < 2; sb++)
#pragma unroll
                for (int hh = 0; hh < 2; hh++) {
                    float vA = pA[mt][sb][hh], vD = pD[mt][sb][hh];
                    vA += __shfl_xor_sync(0xffffffffu, vA, 1);
                    vA += __shfl_xor_sync(0xffffffffu, vA, 2);
                    vD += __shfl_xor_sync(0xffffffffu, vD, 1);
                    vD += __shfl_xor_sync(0xffffffffu, vD, 2);
                    if (tg == 0) {
                        int row = rbase + mt * 16 + sb * 8 + g;
                        int head = (wid & 1) * 2 + hh;
                        spart[row][head][0] = vA;
                        spart[row][head][1] = vD;
                    }
                }
    }

    // ---- store Out (fp32) ----
#pragma unroll
    for (int mt = 0; mt < 2; mt++) {
        int r1 = row0 + rbase + mt * 16 + g;
        int r2 = r1 + 8;
#pragma unroll
        for (int nt = 0; nt < 8; nt++) {
            int c = cbase + nt * 8 + tg * 2;
            if (r1 < nrows)
                *(float2*)&Out[(size_t)r1 * 128 + c] = make_float2(acc[mt][nt][0], acc[mt][nt][1]);
            if (r2 < nrows)
                *(float2*)&Out[(size_t)r2 * 128 + c] = make_float2(acc[mt][nt][2], acc[mt][nt][3]);
        }
    }

    __syncthreads();
    if (tid < 128) {
        int gr = row0 + tid;
        if (gr < nrows) {
            *(float4*)&g_as[gr * 4] = make_float4(spart[tid][0][0], spart[tid][1][0],
                                                  spart[tid][2][0], spart[tid][3][0]);
            *(float4*)&g_ad[gr * 4] = make_float4(spart[tid][0][1], spart[tid][1][1],
                                                  spart[tid][2][1], spart[tid][3][1]);
        }
    }
}

// ---------------- aggregation: one warp per dst node ----------------------------
// deg<=32 fast path: single gather of csr/as, e kept in registers.
// Output written as bf16 hi/lo pair (consumed by next gemm / pool).
__global__ __launch_bounds__(256) void agg_kernel(
    const float* __restrict__ hbuf, const float* __restrict__ bias,
    __nv_bfloat16* __restrict__ outh, __nv_bfloat16* __restrict__ outl)
{
    __shared__ int    s_src[8][32];
    __shared__ float4 s_p[8][32];

    int wi = threadIdx.x >> 5;
    int n = (blockIdx.x * blockDim.x + threadIdx.x) >> 5;
    if (n >= NN) return;
    int lane = threadIdx.x & 31;
    int head = lane >> 3;
    int col = head * 32 + (lane & 7) * 4;

    float4 adv = *(const float4*)&g_ad[n * 4];
    int beg = g_rowoff[n], end = g_rowoff[n + 1];
    int cntA = end - beg;

    float4 acc = make_float4(0.f, 0.f, 0.f, 0.f);
    float4 ss  = acc;

    if (cntA <= 32) {
        // ---- single-pass ----
        bool act = lane < cntA;
        int s = 0;
        float4 ev = make_float4(-1e30f, -1e30f, -1e30f, -1e30f);
        if (act) {
            s = __ldg(&g_csr[beg + lane]);
            float4 a = __ldg((const float4*)&g_as[s * 4]);
            float e;
            e = a.x + adv.x; ev.x = fmaxf(e, NEG * e);
            e = a.y + adv.y; ev.y = fmaxf(e, NEG * e);
            e = a.z + adv.z; ev.z = fmaxf(e, NEG * e);
            e = a.w + adv.w; ev.w = fmaxf(e, NEG * e);
        }
        float4 mx = ev;
#pragma unroll
        for (int off = 16; off; off >>= 1) {
            mx.x = fmaxf(mx.x, __shfl_xor_sync(0xffffffffu, mx.x, off));
            mx.y = fmaxf(mx.y, __shfl_xor_sync(0xffffffffu, mx.y, off));
            mx.z = fmaxf(mx.z, __shfl_xor_sync(0xffffffffu, mx.z, off));
            mx.w = fmaxf(mx.w, __shfl_xor_sync(0xffffffffu, mx.w, off));
        }
        float4 pv = make_float4(0.f, 0.f, 0.f, 0.f);
        if (act) {
            pv.x = __expf(ev.x - mx.x);
            pv.y = __expf(ev.y - mx.y);
            pv.z = __expf(ev.z - mx.z);
            pv.w = __expf(ev.w - mx.w);
            ss = pv;
        }
        s_src[wi][lane] = s;
        s_p[wi][lane] = pv;
        __syncwarp();
        for (int j = 0; j < cntA; j++) {
            int sj = s_src[wi][j];
            float pj = ((const float*)&s_p[wi][j])[head];
            float4 hv = __ldg((const float4*)(hbuf + sj * 128 + col));
            acc.x = fmaf(pj, hv.x, acc.x);
            acc.y = fmaf(pj, hv.y, acc.y);
            acc.z = fmaf(pj, hv.z, acc.z);
            acc.w = fmaf(pj, hv.w, acc.w);
        }
        __syncwarp();
    } else {
        // ---- two-pass (rare: deg > 32) ----
        float4 mx = make_float4(-1e30f, -1e30f, -1e30f, -1e30f);
        for (int p = beg + lane; p < end; p += 32) {
            int s = __ldg(&g_csr[p]);
            float4 a = __ldg((const float4*)&g_as[s * 4]);
            float e;
            e = a.x + adv.x; mx.x = fmaxf(mx.x, fmaxf(e, NEG * e));
            e = a.y + adv.y; mx.y = fmaxf(mx.y, fmaxf(e, NEG * e));
            e = a.z + adv.z; mx.z = fmaxf(mx.z, fmaxf(e, NEG * e));
            e = a.w + adv.w; mx.w = fmaxf(mx.w, fmaxf(e, NEG * e));
        }
#pragma unroll
        for (int off = 16; off; off >>= 1) {
            mx.x = fmaxf(mx.x, __shfl_xor_sync(0xffffffffu, mx.x, off));
            mx.y = fmaxf(mx.y, __shfl_xor_sync(0xffffffffu, mx.y, off));
            mx.z = fmaxf(mx.z, __shfl_xor_sync(0xffffffffu, mx.z, off));
            mx.w = fmaxf(mx.w, __shfl_xor_sync(0xffffffffu, mx.w, off));
        }
        for (int p0 = beg; p0 < end; p0 += 32) {
            int cnt = min(32, end - p0);
            float4 pv = make_float4(0.f, 0.f, 0.f, 0.f);
            int s = 0;
            if (lane < cnt) {
                s = __ldg(&g_csr[p0 + lane]);
                float4 a = __ldg((const float4*)&g_as[s * 4]);
                float e;
                e = a.x + adv.x; e = fmaxf(e, NEG * e); pv.x = __expf(e - mx.x);
                e = a.y + adv.y; e = fmaxf(e, NEG * e); pv.y = __expf(e - mx.y);
                e = a.z + adv.z; e = fmaxf(e, NEG * e); pv.z = __expf(e - mx.z);
                e = a.w + adv.w; e = fmaxf(e, NEG * e); pv.w = __expf(e - mx.w);
                ss.x += pv.x; ss.y += pv.y; ss.z += pv.z; ss.w += pv.w;
            }
            s_src[wi][lane] = s;
            s_p[wi][lane] = pv;
            __syncwarp();
            for (int j = 0; j < cnt; j++) {
                int sj = s_src[wi][j];
                float pj = ((const float*)&s_p[wi][j])[head];
                float4 hv = __ldg((const float4*)(hbuf + sj * 128 + col));
                acc.x = fmaf(pj, hv.x, acc.x);
                acc.y = fmaf(pj, hv.y, acc.y);
                acc.z = fmaf(pj, hv.z, acc.z);
                acc.w = fmaf(pj, hv.w, acc.w);
            }
            __syncwarp();
        }
    }

#pragma unroll
    for (int off = 16; off; off >>= 1) {
        ss.x += __shfl_xor_sync(0xffffffffu, ss.x, off);
        ss.y += __shfl_xor_sync(0xffffffffu, ss.y, off);
        ss.z += __shfl_xor_sync(0xffffffffu, ss.z, off);
        ss.w += __shfl_xor_sync(0xffffffffu, ss.w, off);
    }
    float sh = (head == 0) ? ss.x : (head == 1) ? ss.y : (head == 2) ? ss.z : ss.w;
    float inv = 1.0f / (sh + 1e-16f);

    float4 b = *(const float4*)(bias + col);
    float4 o;
    o.x = acc.x * inv + b.x; o.x = fmaxf(o.x, NEG * o.x);
    o.y = acc.y * inv + b.y; o.y = fmaxf(o.y, NEG * o.y);
    o.z = acc.z * inv + b.z; o.z = fmaxf(o.z, NEG * o.z);
    o.w = acc.w * inv + b.w; o.w = fmaxf(o.w, NEG * o.w);

    __nv_bfloat16 h0, l0, h1, l1, h2, l2, h3, l3;
    bsplit(o.x, h0, l0); bsplit(o.y, h1, l1);
    bsplit(o.z, h2, l2); bsplit(o.w, h3, l3);
    uint32_t ph0 = ((uint32_t)__bfloat16_as_ushort(h1) << 16) | __bfloat16_as_ushort(h0);
    uint32_t ph1 = ((uint32_t)__bfloat16_as_ushort(h3) << 16) | __bfloat16_as_ushort(h2);
    uint32_t pl0 = ((uint32_t)__bfloat16_as_ushort(l1) << 16) | __bfloat16_as_ushort(l0);
    uint32_t pl1 = ((uint32_t)__bfloat16_as_ushort(l3) << 16) | __bfloat16_as_ushort(l2);
    *(uint2*)&outh[(size_t)n * 128 + col] = make_uint2(ph0, ph1);
    *(uint2*)&outl[(size_t)n * 128 + col] = make_uint2(pl0, pl1);
}

// ---------------- pooling: segmented over sorted batch (bf16 hi/lo input) --------
__global__ __launch_bounds__(512) void pool_kernel() {
    __shared__ float sh[3][128];
    int g = blockIdx.x;
    int s = g_goff[g], e = g_goff[g + 1];
    int c = threadIdx.x & 127;
    int r = threadIdx.x >> 7;
    float acc = 0.f;
    for (int i = s + r; i < e; i += 4)
        acc += __bfloat162float(g_yh[(size_t)i * 128 + c]) +
               __bfloat162float(g_yl[(size_t)i * 128 + c]);
    if (r) sh[r - 1][c] = acc;
    __syncthreads();
    if (!r) g_pool[g * 128 + c] = ((acc + sh[0][c]) + (sh[1][c] + sh[2][c]));
}

// ---------------- head ----------------
__global__ void head_kernel(const float* __restrict__ fc_w, const float* __restrict__ fc_b,
                            const float* __restrict__ bn_g, const float* __restrict__ bn_b,
                            float* __restrict__ out)
{
    int g = blockIdx.x;
    int l = threadIdx.x;
    const float* pr = g_pool + g * HID;
    float s = 0.f;
#pragma unroll 8
    for (int k = 0; k < HID; k++) s = fmaf(pr[k], fc_w[k * LAT + l], s);
    s += fc_b[l];
    const float inv = 0.999995000037499688f;  // 1/sqrt(1 + 1e-5)
    out[g * LAT + l] = bn_g[l] * s * inv + bn_b[l];
}

// ---------------- launch ----------------
extern "C" void kernel_launch(void* const* d_in, const int* in_sizes, int n_in,
                              void* d_out, int out_size)
{
    const float* x       = (const float*)d_in[0];
    const int*   eidx    = (const int*)  d_in[1];
    const int*   batch   = (const int*)  d_in[2];
    const float* W0      = (const float*)d_in[3];
    const float* a_src0  = (const float*)d_in[4];
    const float* a_dst0  = (const float*)d_in[5];
    const float* b0      = (const float*)d_in[6];
    const float* W1      = (const float*)d_in[7];
    const float* a_src1  = (const float*)d_in[8];
    const float* a_dst1  = (const float*)d_in[9];
    const float* b1      = (const float*)d_in[10];
    const float* W2      = (const float*)d_in[11];
    const float* a_src2  = (const float*)d_in[12];
    const float* a_dst2  = (const float*)d_in[13];
    const float* b2      = (const float*)d_in[14];
    const float* fc_w    = (const float*)d_in[15];
    const float* fc_b    = (const float*)d_in[16];
    const float* bn_g    = (const float*)d_in[17];
    const float* bn_b    = (const float*)d_in[18];
    float* out = (float*)d_out;

    const int* src = eidx;
    const int* dst = eidx + EE;

    float* ph;
    __nv_bfloat16 *pxh, *pxl, *pyh, *pyl;
    __nv_bfloat16 *pw0h, *pw0l, *pw1h, *pw1l, *pw2h, *pw2l;
    cudaGetSymbolAddress((void**)&ph,  g_h);
    cudaGetSymbolAddress((void**)&pxh, g_xh);
    cudaGetSymbolAddress((void**)&pxl, g_xl);
    cudaGetSymbolAddress((void**)&pyh, g_yh);
    cudaGetSymbolAddress((void**)&pyl, g_yl);
    cudaGetSymbolAddress((void**)&pw0h, g_w0h);
    cudaGetSymbolAddress((void**)&pw0l, g_w0l);
    cudaGetSymbolAddress((void**)&pw1h, g_w1h);
    cudaGetSymbolAddress((void**)&pw1l, g_w1l);
    cudaGetSymbolAddress((void**)&pw2h, g_w2h);
    cudaGetSymbolAddress((void**)&pw2l, g_w2l);

    const int PREP_TOT = NN * XK + 128 * 64 + 2 * 128 * 128;
    const int gemm_grid = (NN + 127) / 128;
    const int warp_grid = (NN + 7) / 8;

    // launch order keeps gemm0 at profiled slot 4; gemm0 independent of CSR.
    prep_kernel<<<(PREP_TOT + 255) / 256, 256>>>(x, W0, W1, W2);
    hist_kernel<<<(EE + 255) / 256, 256>>>(dst);
    scan_kernel<<<1, 1024>>>();
    gemm_kernel<<<gemm_grid, 256>>>(pxh, pxl, pw0h, pw0l, ph, NN, XK, a_src0, a_dst0);
    scatter_kernel<<<(EE + NN + 255) / 256, 256>>>(src, dst);
    agg_kernel<<<warp_grid, 256>>>(ph, b0, pyh, pyl);

    gemm_kernel<<<gemm_grid, 256>>>(pyh, pyl, pw1h, pw1l, ph, NN, HID, a_src1, a_dst1);
    agg_kernel<<<warp_grid, 256>>>(ph, b1, pyh, pyl);

    gemm_kernel<<<gemm_grid, 256>>>(pyh, pyl, pw2h, pw2l, ph, NN, HID, a_src2, a_dst2);
    agg_kernel<<<warp_grid, 256>>>(ph, b2, pyh, pyl);

    gbound_kernel<<<(NN + 255) / 256, 256>>>(batch);
    pool_kernel<<<GG, 512>>>();
    head_kernel<<<GG, LAT>>>(fc_w, fc_b, bn_g, bn_b, out);
}